// round 10
// baseline (speedup 1.0000x reference)
#include <cuda_runtime.h>
#include <cuda_fp16.h>

// ---------------------------------------------------------------------------
// GCN: 3x (GraphConv norm='both') with BN+ReLU between, log_softmax at end.
// N=100000 nodes, E=1.6M edges, D=128, C=40.
//
// Round-10 pipeline (graph-capturable, alloc-free):
//   degrees (int atomics) -> deg^-1/2
//   CSR-by-dst build: parallel 3-phase scan + atomic-cursor fill
//   L1: prep (x * dout -> fp16 rows); prop_fp16 (INTERLEAVED dual-half-warp:
//       half h takes edges h, h+2, ... -> balanced for any degree);
//       gemm128 (128x128 block, 8x8 tile, f32x2, fused BN stats); bn_finalize
//   L2: prep with BN+ReLU; prop_fp16; gemm128; bn_finalize
//   L3: gemm40pre (BN+ReLU on load, @W3, dout scale, f32x2) ->
//       40-wide fp32 prop with fused bias + log_softmax
// ---------------------------------------------------------------------------

#define NMAX 100096
#define EMAX 1600000
#define DD 128
#define CHUNKS 1024

__device__ float   g_bufA[(size_t)NMAX * DD];   // agg buffer / 40-wide t buffer
__device__ float   g_bufB[(size_t)NMAX * DD];   // gemm output / next layer input
__device__ __half2 g_half[(size_t)NMAX * 64];   // fp16 gather copy (256B/row)
__device__ float   g_dout_is[NMAX];
__device__ float   g_din_is[NMAX];
__device__ int     g_deg_out[NMAX];
__device__ int     g_deg_in[NMAX];
__device__ int     g_row_off[NMAX + 1];
__device__ int     g_cursor[NMAX];
__device__ int     g_csr_src[EMAX];
__device__ int     g_chunk_sum[CHUNKS];
__device__ float   g_colsum[DD];  // zero-init; bn_finalize re-zeros after use
__device__ float   g_colsq[DD];
__device__ float   g_bn_a[DD];
__device__ float   g_bn_b[DD];

// packed f32x2 helpers (sm_100+: lowers to FFMA2 / 64-bit regs)
#define FMA_F32X2(d, a, b, c) \
    asm("fma.rn.f32x2 %0, %1, %2, %3;" \
        : "=l"(d) : "l"(a), "l"(b), "l"(c))
#define PACKF2(out, lo, hi) \
    asm("mov.b64 %0, {%1, %2};" \
        : "=l"(out) : "r"(__float_as_uint(lo)), "r"(__float_as_uint(hi)))
#define UNPACKF2(lo, hi, in) \
    do { unsigned int _ulo, _uhi; \
         asm("mov.b64 {%0, %1}, %2;" : "=r"(_ulo), "=r"(_uhi) : "l"(in)); \
         lo = __uint_as_float(_ulo); hi = __uint_as_float(_uhi); } while (0)

// ---------------------------------------------------------------------------
__global__ void zero_deg_kernel(int n) {
    int i = blockIdx.x * blockDim.x + threadIdx.x;
    if (i < n) { g_deg_out[i] = 0; g_deg_in[i] = 0; }
}

__global__ void deg_count_kernel(const int* __restrict__ src,
                                 const int* __restrict__ dst, int E) {
    int i = blockIdx.x * blockDim.x + threadIdx.x;
    if (i < E) {
        atomicAdd(&g_deg_out[src[i]], 1);
        atomicAdd(&g_deg_in[dst[i]], 1);
    }
}

__global__ void deg_inv_kernel(int n) {
    int i = blockIdx.x * blockDim.x + threadIdx.x;
    if (i < n) {
        g_dout_is[i] = rsqrtf(fmaxf((float)g_deg_out[i], 1.f));
        g_din_is[i]  = rsqrtf(fmaxf((float)g_deg_in[i], 1.f));
    }
}

// ---------------------------------------------------------------------------
// Parallel exclusive scan of deg_in -> row_off (3 phases, full-chip).
// ---------------------------------------------------------------------------
__global__ void __launch_bounds__(256) chunk_sum_kernel(int N, int chunk) {
    int w = blockIdx.x * 8 + (threadIdx.x >> 5);
    if (w >= CHUNKS) return;
    int lane = threadIdx.x & 31;
    int lo = w * chunk, hi = min(lo + chunk, N);
    int s = 0;
    for (int i = lo + lane; i < hi; i += 32) s += g_deg_in[i];
    #pragma unroll
    for (int off = 16; off; off >>= 1)
        s += __shfl_down_sync(0xffffffffu, s, off);
    if (lane == 0) g_chunk_sum[w] = s;
}

__global__ void __launch_bounds__(1024) scan_chunks_kernel(int N) {
    __shared__ int sdata[1024];
    int t = threadIdx.x;
    int v = g_chunk_sum[t];
    sdata[t] = v;
    __syncthreads();
    #pragma unroll
    for (int off = 1; off < 1024; off <<= 1) {
        int u = (t >= off) ? sdata[t - off] : 0;
        __syncthreads();
        sdata[t] += u;
        __syncthreads();
    }
    g_chunk_sum[t] = sdata[t] - v;          // exclusive prefix per chunk
    if (t == 1023) g_row_off[N] = sdata[1023];
}

__global__ void __launch_bounds__(256) fill_off_kernel(int N, int chunk) {
    int w = blockIdx.x * 8 + (threadIdx.x >> 5);
    if (w >= CHUNKS) return;
    int lane = threadIdx.x & 31;
    int lo = w * chunk, hi = min(lo + chunk, N);
    int run = g_chunk_sum[w];
    for (int base = lo; base < hi; base += 32) {
        int i = base + lane;
        int v = (i < hi) ? __ldg(&g_deg_in[i]) : 0;
        int incl = v;
        #pragma unroll
        for (int off = 1; off < 32; off <<= 1) {
            int t = __shfl_up_sync(0xffffffffu, incl, off);
            if (lane >= off) incl += t;
        }
        if (i < hi) {
            int off_i = run + incl - v;
            g_row_off[i] = off_i;
            g_cursor[i]  = off_i;
        }
        run += __shfl_sync(0xffffffffu, incl, 31);
    }
}

__global__ void csr_fill_kernel(const int* __restrict__ src,
                                const int* __restrict__ dst, int E) {
    int i = blockIdx.x * blockDim.x + threadIdx.x;
    if (i < E) {
        int pos = atomicAdd(&g_cursor[dst[i]], 1);
        g_csr_src[pos] = src[i];
    }
}

// ---------------------------------------------------------------------------
// Prep: per-node (not per-edge!) BN+ReLU + dout scaling, emit fp16 rows.
// ---------------------------------------------------------------------------
template <int USE_BN>
__global__ void __launch_bounds__(256) prep_kernel(
    const float4* __restrict__ in, __half2* __restrict__ outh, int N)
{
    int i = blockIdx.x * blockDim.x + threadIdx.x;
    if (i >= N * 32) return;
    int node = i >> 5;
    int q    = i & 31;
    float4 v = __ldg(in + i);
    if (USE_BN) {
        float4 a = __ldg(((const float4*)g_bn_a) + q);
        float4 b = __ldg(((const float4*)g_bn_b) + q);
        v.x = fmaxf(fmaf(v.x, a.x, b.x), 0.f);
        v.y = fmaxf(fmaf(v.y, a.y, b.y), 0.f);
        v.z = fmaxf(fmaf(v.z, a.z, b.z), 0.f);
        v.w = fmaxf(fmaf(v.w, a.w, b.w), 0.f);
    }
    float sc = __ldg(&g_dout_is[node]);
    outh[i * 2 + 0] = __floats2half2_rn(v.x * sc, v.y * sc);
    outh[i * 2 + 1] = __floats2half2_rn(v.z * sc, v.w * sc);
}

// ---------------------------------------------------------------------------
// fp16 CSR propagation, INTERLEAVED dual-half-warp: one warp per dst node.
// Lane (h, hl) owns features [8*hl, 8*hl+8) (one uint4 = 256B row / 16 lanes).
// Index staging is PERMUTED: lane (h, hl) holds edge 2*hl+h of the batch, so
// half h processes edges h, h+2, h+4, ... -> balanced for any n (diff <= 1),
// and shfl sources stay inside each half's mask. Halves merge via shfl_xor(16).
// Per edge only 16 lanes issue the row load -> half the warp-LDG count.
// ---------------------------------------------------------------------------
__global__ void __launch_bounds__(256) prop_fp16_kernel(
    const uint4* __restrict__ inh, float* __restrict__ out, int N)
{
    int node = blockIdx.x * 8 + (threadIdx.x >> 5);
    if (node >= N) return;
    int lane = threadIdx.x & 31;
    int half = lane >> 4;                       // 0 or 1
    int hl   = lane & 15;                       // lane within half
    unsigned hmask = half ? 0xffff0000u : 0x0000ffffu;
    int lob  = half << 4;
    int start = __ldg(&g_row_off[node]);
    int end   = __ldg(&g_row_off[node + 1]);

    float acc[8];
    #pragma unroll
    for (int i = 0; i < 8; i++) acc[i] = 0.f;

    for (int base = start; base < end; base += 32) {
        int n = min(32, end - base);
        int eidx = 2 * hl + half;               // permuted staging index
        int s = 0;
        if (eidx < n) s = __ldg(g_csr_src + base + eidx);
        int cnt = (n - half + 1) >> 1;          // edges for this half
        int j = 0;
        for (; j + 4 <= cnt; j += 4) {
            int s0 = __shfl_sync(hmask, s, lob + j);
            int s1 = __shfl_sync(hmask, s, lob + j + 1);
            int s2 = __shfl_sync(hmask, s, lob + j + 2);
            int s3 = __shfl_sync(hmask, s, lob + j + 3);
            uint4 r0 = __ldg(inh + (size_t)s0 * 16 + hl);
            uint4 r1 = __ldg(inh + (size_t)s1 * 16 + hl);
            uint4 r2 = __ldg(inh + (size_t)s2 * 16 + hl);
            uint4 r3 = __ldg(inh + (size_t)s3 * 16 + hl);
            #pragma unroll
            for (int q = 0; q < 4; q++) {
                uint4 r = q == 0 ? r0 : (q == 1 ? r1 : (q == 2 ? r2 : r3));
                float2 f0 = __half22float2(*(const __half2*)&r.x);
                float2 f1 = __half22float2(*(const __half2*)&r.y);
                float2 f2 = __half22float2(*(const __half2*)&r.z);
                float2 f3 = __half22float2(*(const __half2*)&r.w);
                acc[0] += f0.x; acc[1] += f0.y;
                acc[2] += f1.x; acc[3] += f1.y;
                acc[4] += f2.x; acc[5] += f2.y;
                acc[6] += f3.x; acc[7] += f3.y;
            }
        }
        for (; j < cnt; j++) {
            int sj = __shfl_sync(hmask, s, lob + j);
            uint4 r = __ldg(inh + (size_t)sj * 16 + hl);
            float2 f0 = __half22float2(*(const __half2*)&r.x);
            float2 f1 = __half22float2(*(const __half2*)&r.y);
            float2 f2 = __half22float2(*(const __half2*)&r.z);
            float2 f3 = __half22float2(*(const __half2*)&r.w);
            acc[0] += f0.x; acc[1] += f0.y;
            acc[2] += f1.x; acc[3] += f1.y;
            acc[4] += f2.x; acc[5] += f2.y;
            acc[6] += f3.x; acc[7] += f3.y;
        }
    }

    __syncwarp();
    #pragma unroll
    for (int i = 0; i < 8; i++)
        acc[i] += __shfl_xor_sync(0xffffffffu, acc[i], 16);

    if (half == 0) {
        float4* op = (float4*)out + (size_t)node * 32 + hl * 2;
        op[0] = make_float4(acc[0], acc[1], acc[2], acc[3]);
        op[1] = make_float4(acc[4], acc[5], acc[6], acc[7]);
    }
}

// ---------------------------------------------------------------------------
// GEMM: out[r,c] = din_is[r] * (A[r,:] @ W[:,c]) + bias[c], D=128 square,
// with BN column stats fused into the epilogue.
// Block: 128 rows x 128 cols, 256 threads, 8x8 per thread (halves LDS/FMA
// vs 8x4). f32x2 packed FMA over row pairs. 1 block/SM (132KB smem).
// ---------------------------------------------------------------------------
#define SMEM128 ((128 * 128 + 128 * 132 + 256) * 4)

__global__ void __launch_bounds__(256, 1) gemm128_kernel(
    const float* __restrict__ A, const float* __restrict__ W,
    const float* __restrict__ bias, float* __restrict__ out, int N)
{
    extern __shared__ float sm[];
    float* sW   = sm;                        // [k][c], 128*128
    float* sAT  = sm + 128 * 128;            // [k][r], leading dim 132
    float* sSum = sAT + 128 * 132;           // [128]
    float* sSq  = sSum + 128;                // [128]
    int tid  = threadIdx.x;
    int row0 = blockIdx.x * 128;

    if (tid < 128) { sSum[tid] = 0.f; sSq[tid] = 0.f; }

    {
        const float4* W4 = (const float4*)W;
        float4* sW4 = (float4*)sW;
        #pragma unroll
        for (int i = 0; i < 16; i++) sW4[tid + i * 256] = __ldg(W4 + tid + i * 256);
    }
    #pragma unroll
    for (int ii = 0; ii < 16; ii++) {
        int i  = tid + ii * 256;           // 4096 float4 total (128 rows)
        int r  = i >> 5;
        int k4 = (i & 31) << 2;
        int rr = row0 + r;
        float4 v = make_float4(0.f, 0.f, 0.f, 0.f);
        if (rr < N) v = __ldg((const float4*)(A + (size_t)rr * 128 + k4));
        sAT[(k4 + 0) * 132 + r] = v.x;
        sAT[(k4 + 1) * 132 + r] = v.y;
        sAT[(k4 + 2) * 132 + r] = v.z;
        sAT[(k4 + 3) * 132 + r] = v.w;
    }
    __syncthreads();

    int cg = (tid & 15) << 3;   // cols [cg, cg+8)
    int rg = (tid >> 4) << 3;   // rows [rg, rg+8)

    // accp[pr][j]: f32x2 accumulator (rows rg+2pr, rg+2pr+1) x col cg+j
    unsigned long long accp[4][8];
    #pragma unroll
    for (int pr = 0; pr < 4; pr++)
        #pragma unroll
        for (int j = 0; j < 8; j++) accp[pr][j] = 0ull;

    #pragma unroll 4
    for (int k = 0; k < 128; k++) {
        const ulonglong2* apt = (const ulonglong2*)(sAT + k * 132 + rg);
        ulonglong2 a01 = apt[0];
        ulonglong2 a23 = apt[1];
        unsigned long long ap[4] = {a01.x, a01.y, a23.x, a23.y};
        float4 w0 = *(const float4*)(sW + k * 128 + cg);
        float4 w1 = *(const float4*)(sW + k * 128 + cg + 4);
        unsigned long long wd[8];
        PACKF2(wd[0], w0.x, w0.x);
        PACKF2(wd[1], w0.y, w0.y);
        PACKF2(wd[2], w0.z, w0.z);
        PACKF2(wd[3], w0.w, w0.w);
        PACKF2(wd[4], w1.x, w1.x);
        PACKF2(wd[5], w1.y, w1.y);
        PACKF2(wd[6], w1.z, w1.z);
        PACKF2(wd[7], w1.w, w1.w);
        #pragma unroll
        for (int pr = 0; pr < 4; pr++)
            #pragma unroll
            for (int j = 0; j < 8; j++)
                FMA_F32X2(accp[pr][j], ap[pr], wd[j], accp[pr][j]);
    }

    float4 bv0 = __ldg((const float4*)(bias + cg));
    float4 bv1 = __ldg((const float4*)(bias + cg + 4));
    float bb[8] = {bv0.x, bv0.y, bv0.z, bv0.w, bv1.x, bv1.y, bv1.z, bv1.w};
    float csum[8] = {0,0,0,0,0,0,0,0};
    float csq[8]  = {0,0,0,0,0,0,0,0};

    #pragma unroll
    for (int pr = 0; pr < 4; pr++) {
        int r0i = row0 + rg + 2 * pr;
        int r1i = r0i + 1;
        float o0[8], o1[8];
        float sc0 = (r0i < N) ? __ldg(&g_din_is[r0i]) : 0.f;
        float sc1 = (r1i < N) ? __ldg(&g_din_is[r1i]) : 0.f;
        #pragma unroll
        for (int j = 0; j < 8; j++) {
            float lo, hi;
            UNPACKF2(lo, hi, accp[pr][j]);
            o0[j] = fmaf(lo, sc0, bb[j]);
            o1[j] = fmaf(hi, sc1, bb[j]);
        }
        if (r0i < N) {
            #pragma unroll
            for (int j = 0; j < 8; j++) {
                csum[j] += o0[j]; csq[j] = fmaf(o0[j], o0[j], csq[j]);
            }
            float* p = out + (size_t)r0i * 128 + cg;
            *(float4*)p       = make_float4(o0[0], o0[1], o0[2], o0[3]);
            *(float4*)(p + 4) = make_float4(o0[4], o0[5], o0[6], o0[7]);
        }
        if (r1i < N) {
            #pragma unroll
            for (int j = 0; j < 8; j++) {
                csum[j] += o1[j]; csq[j] = fmaf(o1[j], o1[j], csq[j]);
            }
            float* p = out + (size_t)r1i * 128 + cg;
            *(float4*)p       = make_float4(o1[0], o1[1], o1[2], o1[3]);
            *(float4*)(p + 4) = make_float4(o1[4], o1[5], o1[6], o1[7]);
        }
    }
    #pragma unroll
    for (int j = 0; j < 8; j++) {
        atomicAdd(&sSum[cg + j], csum[j]);
        atomicAdd(&sSq[cg + j],  csq[j]);
    }
    __syncthreads();
    if (tid < 128) {
        atomicAdd(&g_colsum[tid], sSum[tid]);
        atomicAdd(&g_colsq[tid],  sSq[tid]);
    }
}

__global__ void bn_finalize_kernel(const float* __restrict__ g,
                                   const float* __restrict__ be, float invN) {
    int c = threadIdx.x;  // 128 threads
    float mu  = g_colsum[c] * invN;
    float var = fmaf(-mu, mu, g_colsq[c] * invN);
    float a   = __ldg(g + c) * rsqrtf(var + 1e-5f);
    g_bn_a[c] = a;
    g_bn_b[c] = fmaf(-mu, a, __ldg(be + c));
    g_colsum[c] = 0.f;  // reset for next BN / next launch
    g_colsq[c]  = 0.f;
}

// ---------------------------------------------------------------------------
// Layer-3 pre-prop GEMM: t[r, 0..39] = dout_is[r] * (relu(bn(A[r,:])) @ W3).
// BN+ReLU applied while staging A. f32x2 packed FMA over row pairs.
// ---------------------------------------------------------------------------
#define SMEM40 ((128 * 64 + 128 * 68) * 4)

__global__ void __launch_bounds__(256) gemm40pre_kernel(
    const float* __restrict__ A, const float* __restrict__ W3,
    float* __restrict__ t, int N)
{
    extern __shared__ float sm[];
    float* sW   = sm;                       // [k][c] padded to 64 cols
    float* sAT  = sm + 128 * 64;            // [k][r] ld 68
    int tid  = threadIdx.x;
    int row0 = blockIdx.x * 64;

    for (int i = tid; i < 128 * 64; i += 256) sW[i] = 0.f;
    __syncthreads();
    for (int i = tid; i < 128 * 40; i += 256) {
        int k = i / 40, c = i - k * 40;
        sW[k * 64 + c] = __ldg(W3 + i);
    }
    #pragma unroll
    for (int ii = 0; ii < 8; ii++) {
        int i  = tid + ii * 256;
        int r  = i >> 5;
        int k4 = (i & 31) << 2;
        int rr = row0 + r;
        float4 v = make_float4(0.f, 0.f, 0.f, 0.f);
        if (rr < N) v = __ldg((const float4*)(A + (size_t)rr * 128 + k4));
        float4 a = __ldg(((const float4*)g_bn_a) + (k4 >> 2));
        float4 b = __ldg(((const float4*)g_bn_b) + (k4 >> 2));
        sAT[(k4 + 0) * 68 + r] = fmaxf(fmaf(v.x, a.x, b.x), 0.f);
        sAT[(k4 + 1) * 68 + r] = fmaxf(fmaf(v.y, a.y, b.y), 0.f);
        sAT[(k4 + 2) * 68 + r] = fmaxf(fmaf(v.z, a.z, b.z), 0.f);
        sAT[(k4 + 3) * 68 + r] = fmaxf(fmaf(v.w, a.w, b.w), 0.f);
    }
    __syncthreads();

    int cg = (tid & 15) << 2;   // cols [cg, cg+4) of 64 (only <40 real)
    int rg = (tid >> 4) << 2;   // rows [rg, rg+4)

    unsigned long long accp[2][4];   // row pairs (rg,rg+1),(rg+2,rg+3)
    #pragma unroll
    for (int pr = 0; pr < 2; pr++)
        #pragma unroll
        for (int j = 0; j < 4; j++) accp[pr][j] = 0ull;

    #pragma unroll 8
    for (int k = 0; k < 128; k++) {
        float4 wv = *(const float4*)(sW + k * 64 + cg);
        ulonglong2 a01 = *(const ulonglong2*)(sAT + k * 68 + rg);
        unsigned long long ap[2] = {a01.x, a01.y};
        unsigned long long wd[4];
        PACKF2(wd[0], wv.x, wv.x);
        PACKF2(wd[1], wv.y, wv.y);
        PACKF2(wd[2], wv.z, wv.z);
        PACKF2(wd[3], wv.w, wv.w);
        #pragma unroll
        for (int pr = 0; pr < 2; pr++)
            #pragma unroll
            for (int j = 0; j < 4; j++)
                FMA_F32X2(accp[pr][j], ap[pr], wd[j], accp[pr][j]);
    }

    float acc[4][4];
    #pragma unroll
    for (int pr = 0; pr < 2; pr++)
        #pragma unroll
        for (int j = 0; j < 4; j++) {
            float lo, hi;
            UNPACKF2(lo, hi, accp[pr][j]);
            acc[2 * pr + 0][j] = lo;
            acc[2 * pr + 1][j] = hi;
        }

    if (cg < 40) {
        #pragma unroll
        for (int i = 0; i < 4; i++) {
            int rr = row0 + rg + i;
            if (rr < N) {
                float sc = __ldg(&g_dout_is[rr]);
                float4 o;
                o.x = acc[i][0] * sc;
                o.y = acc[i][1] * sc;
                o.z = acc[i][2] * sc;
                o.w = acc[i][3] * sc;
                *(float4*)(t + (size_t)rr * 40 + cg) = o;
            }
        }
    }
}

// ---------------------------------------------------------------------------
// 40-wide CSR propagation + bias + log_softmax. One warp per dst node.
// Lanes 0..9 each own 4 of the 40 features (float4, fp32 for final precision).
// ---------------------------------------------------------------------------
__global__ void __launch_bounds__(256) prop40_kernel(
    const float* __restrict__ t, const float* __restrict__ b3,
    float* __restrict__ out, int N)
{
    int node = blockIdx.x * 8 + (threadIdx.x >> 5);
    if (node >= N) return;
    int lane = threadIdx.x & 31;
    bool act = lane < 10;
    int start = __ldg(&g_row_off[node]);
    int end   = __ldg(&g_row_off[node + 1]);

    float4 acc = make_float4(0.f, 0.f, 0.f, 0.f);
    for (int base = start; base < end; base += 32) {
        int n = min(32, end - base);
        int s = 0;
        if (lane < n) s = __ldg(g_csr_src + base + lane);
        int j = 0;
        for (; j + 4 <= n; j += 4) {
            int s0 = __shfl_sync(0xffffffffu, s, j);
            int s1 = __shfl_sync(0xffffffffu, s, j + 1);
            int s2 = __shfl_sync(0xffffffffu, s, j + 2);
            int s3 = __shfl_sync(0xffffffffu, s, j + 3);
            if (act) {
                float4 v0 = __ldg((const float4*)(t + (size_t)s0 * 40) + lane);
                float4 v1 = __ldg((const float4*)(t + (size_t)s1 * 40) + lane);
                float4 v2 = __ldg((const float4*)(t + (size_t)s2 * 40) + lane);
                float4 v3 = __ldg((const float4*)(t + (size_t)s3 * 40) + lane);
                acc.x += v0.x + v1.x + v2.x + v3.x;
                acc.y += v0.y + v1.y + v2.y + v3.y;
                acc.z += v0.z + v1.z + v2.z + v3.z;
                acc.w += v0.w + v1.w + v2.w + v3.w;
            }
        }
        for (; j < n; j++) {
            int sj = __shfl_sync(0xffffffffu, s, j);
            if (act) {
                float4 v = __ldg((const float4*)(t + (size_t)sj * 40) + lane);
                acc.x += v.x; acc.y += v.y; acc.z += v.z; acc.w += v.w;
            }
        }
    }

    float din = __ldg(&g_din_is[node]);
    float4 o = make_float4(0.f, 0.f, 0.f, 0.f);
    if (act) {
        float4 bv = __ldg(((const float4*)b3) + lane);
        o.x = fmaf(acc.x, din, bv.x);
        o.y = fmaf(acc.y, din, bv.y);
        o.z = fmaf(acc.z, din, bv.z);
        o.w = fmaf(acc.w, din, bv.w);
    }
    float m = act ? fmaxf(fmaxf(o.x, o.y), fmaxf(o.z, o.w)) : -1e30f;
    #pragma unroll
    for (int off = 16; off; off >>= 1)
        m = fmaxf(m, __shfl_xor_sync(0xffffffffu, m, off));
    float e = act ? (expf(o.x - m) + expf(o.y - m) +
                     expf(o.z - m) + expf(o.w - m)) : 0.f;
    #pragma unroll
    for (int off = 16; off; off >>= 1)
        e += __shfl_xor_sync(0xffffffffu, e, off);
    float lse = m + logf(e);
    if (act) {
        float4 r;
        r.x = o.x - lse; r.y = o.y - lse; r.z = o.z - lse; r.w = o.w - lse;
        *(float4*)(out + (size_t)node * 40 + lane * 4) = r;
    }
}

// ---------------------------------------------------------------------------
extern "C" void kernel_launch(void* const* d_in, const int* in_sizes, int n_in,
                              void* d_out, int out_size)
{
    const float* x   = (const float*)d_in[0];
    const int*   src = (const int*)d_in[1];
    const int*   dst = (const int*)d_in[2];
    const float* W1  = (const float*)d_in[3];
    const float* b1  = (const float*)d_in[4];
    const float* g1  = (const float*)d_in[5];
    const float* be1 = (const float*)d_in[6];
    const float* W2  = (const float*)d_in[7];
    const float* b2  = (const float*)d_in[8];
    const float* g2  = (const float*)d_in[9];
    const float* be2 = (const float*)d_in[10];
    const float* W3  = (const float*)d_in[11];
    const float* b3  = (const float*)d_in[12];

    int N = in_sizes[0] / DD;
    int E = in_sizes[1];
    float* out = (float*)d_out;

    float *bufA, *bufB;
    __half2* bufH;
    cudaGetSymbolAddress((void**)&bufA, g_bufA);
    cudaGetSymbolAddress((void**)&bufB, g_bufB);
    cudaGetSymbolAddress((void**)&bufH, g_half);

    cudaFuncSetAttribute(gemm128_kernel,
                         cudaFuncAttributeMaxDynamicSharedMemorySize, SMEM128);
    cudaFuncSetAttribute(gemm40pre_kernel,
                         cudaFuncAttributeMaxDynamicSharedMemorySize, SMEM40);

    int ngrid  = (N + 255) / 256;
    int egrid  = (E + 255) / 256;
    int pgrid  = (N + 7) / 8;          // 8 warps (nodes) per 256-thread block
    int qgrid  = (N * 32 + 255) / 256; // prep: one thread per float4
    int g128   = (N + 127) / 128;      // gemm128: 128-row blocks
    int g64    = (N + 63) / 64;        // gemm40pre: 64-row blocks
    int chunk  = (N + CHUNKS - 1) / CHUNKS;
    float invN = 1.0f / (float)N;

    // degrees + CSR-by-dst
    zero_deg_kernel<<<ngrid, 256>>>(N);
    deg_count_kernel<<<egrid, 256>>>(src, dst, E);
    deg_inv_kernel<<<ngrid, 256>>>(N);
    chunk_sum_kernel<<<CHUNKS / 8, 256>>>(N, chunk);
    scan_chunks_kernel<<<1, 1024>>>(N);
    fill_off_kernel<<<CHUNKS / 8, 256>>>(N, chunk);
    csr_fill_kernel<<<egrid, 256>>>(src, dst, E);

    // layer 1
    prep_kernel<0><<<qgrid, 256>>>((const float4*)x, bufH, N);
    prop_fp16_kernel<<<pgrid, 256>>>((const uint4*)bufH, bufA, N);
    gemm128_kernel<<<g128, 256, SMEM128>>>(bufA, W1, b1, bufB, N);
    bn_finalize_kernel<<<1, 128>>>(g1, be1, invN);

    // layer 2
    prep_kernel<1><<<qgrid, 256>>>((const float4*)bufB, bufH, N);
    prop_fp16_kernel<<<pgrid, 256>>>((const uint4*)bufH, bufA, N);
    gemm128_kernel<<<g128, 256, SMEM128>>>(bufA, W2, b2, bufB, N);
    bn_finalize_kernel<<<1, 128>>>(g2, be2, invN);

    // layer 3: GEMM first (prop and @W3 commute), then 40-wide prop
    //          with fused bias + log_softmax (fp32 for output precision)
    gemm40pre_kernel<<<g64, 256, SMEM40>>>(bufB, W3, bufA, N);
    prop40_kernel<<<pgrid, 256>>>(bufA, b3, out, N);
}

// round 11
// speedup vs baseline: 1.1777x; 1.1777x over previous
#include <cuda_runtime.h>
#include <cuda_fp16.h>

// ---------------------------------------------------------------------------
// GCN: 3x (GraphConv norm='both') with BN+ReLU between, log_softmax at end.
// N=100000 nodes, E=1.6M edges, D=128, C=40.
//
// Round-11 = Round-8 baseline (best: 476us) + prop MLP 4 -> 8 + MLP-4 tail.
// (Half-warp prop variants of R9/R10 falsified twice -> reverted.)
//
// Pipeline (graph-capturable, alloc-free):
//   degrees (int atomics) -> deg^-1/2
//   CSR-by-dst build: parallel 3-phase scan + atomic-cursor fill
//   L1: prep (x * dout -> fp16 rows); prop_fp16 (warp/node, MLP-8 pipelined
//       LDG.64 gathers, fp32 accum); gemm128 (f32x2, fused BN stats); finalize
//   L2: prep with BN+ReLU; prop_fp16; gemm128 (fused stats); finalize
//   L3: gemm40pre (BN+ReLU on load, @W3, dout scale, f32x2) ->
//       40-wide fp32 prop with fused bias + log_softmax
// ---------------------------------------------------------------------------

#define NMAX 100096
#define EMAX 1600000
#define DD 128
#define CHUNKS 1024

__device__ float   g_bufA[(size_t)NMAX * DD];   // agg buffer / 40-wide t buffer
__device__ float   g_bufB[(size_t)NMAX * DD];   // gemm output / next layer input
__device__ __half2 g_half[(size_t)NMAX * 64];   // fp16 gather copy (256B/row)
__device__ float   g_dout_is[NMAX];
__device__ float   g_din_is[NMAX];
__device__ int     g_deg_out[NMAX];
__device__ int     g_deg_in[NMAX];
__device__ int     g_row_off[NMAX + 1];
__device__ int     g_cursor[NMAX];
__device__ int     g_csr_src[EMAX];
__device__ int     g_chunk_sum[CHUNKS];
__device__ float   g_colsum[DD];  // zero-init; bn_finalize re-zeros after use
__device__ float   g_colsq[DD];
__device__ float   g_bn_a[DD];
__device__ float   g_bn_b[DD];

// packed f32x2 helpers (sm_100+: lowers to FFMA2 / 64-bit regs)
#define FMA_F32X2(d, a, b, c) \
    asm("fma.rn.f32x2 %0, %1, %2, %3;" \
        : "=l"(d) : "l"(a), "l"(b), "l"(c))
#define PACKF2(out, lo, hi) \
    asm("mov.b64 %0, {%1, %2};" \
        : "=l"(out) : "r"(__float_as_uint(lo)), "r"(__float_as_uint(hi)))
#define UNPACKF2(lo, hi, in) \
    do { unsigned int _ulo, _uhi; \
         asm("mov.b64 {%0, %1}, %2;" : "=r"(_ulo), "=r"(_uhi) : "l"(in)); \
         lo = __uint_as_float(_ulo); hi = __uint_as_float(_uhi); } while (0)

// ---------------------------------------------------------------------------
__global__ void zero_deg_kernel(int n) {
    int i = blockIdx.x * blockDim.x + threadIdx.x;
    if (i < n) { g_deg_out[i] = 0; g_deg_in[i] = 0; }
}

__global__ void deg_count_kernel(const int* __restrict__ src,
                                 const int* __restrict__ dst, int E) {
    int i = blockIdx.x * blockDim.x + threadIdx.x;
    if (i < E) {
        atomicAdd(&g_deg_out[src[i]], 1);
        atomicAdd(&g_deg_in[dst[i]], 1);
    }
}

__global__ void deg_inv_kernel(int n) {
    int i = blockIdx.x * blockDim.x + threadIdx.x;
    if (i < n) {
        g_dout_is[i] = rsqrtf(fmaxf((float)g_deg_out[i], 1.f));
        g_din_is[i]  = rsqrtf(fmaxf((float)g_deg_in[i], 1.f));
    }
}

// ---------------------------------------------------------------------------
// Parallel exclusive scan of deg_in -> row_off (3 phases, full-chip).
// ---------------------------------------------------------------------------
__global__ void __launch_bounds__(256) chunk_sum_kernel(int N, int chunk) {
    int w = blockIdx.x * 8 + (threadIdx.x >> 5);
    if (w >= CHUNKS) return;
    int lane = threadIdx.x & 31;
    int lo = w * chunk, hi = min(lo + chunk, N);
    int s = 0;
    for (int i = lo + lane; i < hi; i += 32) s += g_deg_in[i];
    #pragma unroll
    for (int off = 16; off; off >>= 1)
        s += __shfl_down_sync(0xffffffffu, s, off);
    if (lane == 0) g_chunk_sum[w] = s;
}

__global__ void __launch_bounds__(1024) scan_chunks_kernel(int N) {
    __shared__ int sdata[1024];
    int t = threadIdx.x;
    int v = g_chunk_sum[t];
    sdata[t] = v;
    __syncthreads();
    #pragma unroll
    for (int off = 1; off < 1024; off <<= 1) {
        int u = (t >= off) ? sdata[t - off] : 0;
        __syncthreads();
        sdata[t] += u;
        __syncthreads();
    }
    g_chunk_sum[t] = sdata[t] - v;          // exclusive prefix per chunk
    if (t == 1023) g_row_off[N] = sdata[1023];
}

__global__ void __launch_bounds__(256) fill_off_kernel(int N, int chunk) {
    int w = blockIdx.x * 8 + (threadIdx.x >> 5);
    if (w >= CHUNKS) return;
    int lane = threadIdx.x & 31;
    int lo = w * chunk, hi = min(lo + chunk, N);
    int run = g_chunk_sum[w];
    for (int base = lo; base < hi; base += 32) {
        int i = base + lane;
        int v = (i < hi) ? __ldg(&g_deg_in[i]) : 0;
        int incl = v;
        #pragma unroll
        for (int off = 1; off < 32; off <<= 1) {
            int t = __shfl_up_sync(0xffffffffu, incl, off);
            if (lane >= off) incl += t;
        }
        if (i < hi) {
            int off_i = run + incl - v;
            g_row_off[i] = off_i;
            g_cursor[i]  = off_i;
        }
        run += __shfl_sync(0xffffffffu, incl, 31);
    }
}

__global__ void csr_fill_kernel(const int* __restrict__ src,
                                const int* __restrict__ dst, int E) {
    int i = blockIdx.x * blockDim.x + threadIdx.x;
    if (i < E) {
        int pos = atomicAdd(&g_cursor[dst[i]], 1);
        g_csr_src[pos] = src[i];
    }
}

// ---------------------------------------------------------------------------
// Prep: per-node (not per-edge!) BN+ReLU + dout scaling, emit fp16 rows.
// One thread per float4 (4 features). Coalesced read + write.
// ---------------------------------------------------------------------------
template <int USE_BN>
__global__ void __launch_bounds__(256) prep_kernel(
    const float4* __restrict__ in, __half2* __restrict__ outh, int N)
{
    int i = blockIdx.x * blockDim.x + threadIdx.x;
    if (i >= N * 32) return;
    int node = i >> 5;
    int q    = i & 31;
    float4 v = __ldg(in + i);
    if (USE_BN) {
        float4 a = __ldg(((const float4*)g_bn_a) + q);
        float4 b = __ldg(((const float4*)g_bn_b) + q);
        v.x = fmaxf(fmaf(v.x, a.x, b.x), 0.f);
        v.y = fmaxf(fmaf(v.y, a.y, b.y), 0.f);
        v.z = fmaxf(fmaf(v.z, a.z, b.z), 0.f);
        v.w = fmaxf(fmaf(v.w, a.w, b.w), 0.f);
    }
    float sc = __ldg(&g_dout_is[node]);
    outh[i * 2 + 0] = __floats2half2_rn(v.x * sc, v.y * sc);
    outh[i * 2 + 1] = __floats2half2_rn(v.z * sc, v.w * sc);
}

// ---------------------------------------------------------------------------
// fp16 CSR propagation: one warp per dst node. Lane l owns features
// [4l, 4l+4) as one uint2 (2x half2, 8B). Pure sum, fp32 accumulation.
// Inner loop unrolled x8 (8 independent LDG.64 in flight), then an MLP-4
// tail, then singles. Props are latency-exposed (floor ~50us, measured
// ~130us at MLP-4) -> deepen the pipeline.
// ---------------------------------------------------------------------------
__device__ __forceinline__ void acc_row(float4& acc, uint2 r) {
    float2 a = __half22float2(*(const __half2*)&r.x);
    float2 b = __half22float2(*(const __half2*)&r.y);
    acc.x += a.x; acc.y += a.y; acc.z += b.x; acc.w += b.y;
}

__global__ void __launch_bounds__(256) prop_fp16_kernel(
    const uint2* __restrict__ inh, float* __restrict__ out, int N)
{
    int node = blockIdx.x * 8 + (threadIdx.x >> 5);
    if (node >= N) return;
    int lane = threadIdx.x & 31;
    int start = __ldg(&g_row_off[node]);
    int end   = __ldg(&g_row_off[node + 1]);

    float4 acc = make_float4(0.f, 0.f, 0.f, 0.f);
    for (int base = start; base < end; base += 32) {
        int n = min(32, end - base);
        int s = 0;
        if (lane < n) s = __ldg(g_csr_src + base + lane);
        int j = 0;
        for (; j + 8 <= n; j += 8) {
            int si[8];
            #pragma unroll
            for (int q = 0; q < 8; q++)
                si[q] = __shfl_sync(0xffffffffu, s, j + q);
            uint2 r[8];
            #pragma unroll
            for (int q = 0; q < 8; q++)
                r[q] = __ldg(inh + (size_t)si[q] * 32 + lane);
            #pragma unroll
            for (int q = 0; q < 8; q++)
                acc_row(acc, r[q]);
        }
        if (j + 4 <= n) {
            int si[4];
            #pragma unroll
            for (int q = 0; q < 4; q++)
                si[q] = __shfl_sync(0xffffffffu, s, j + q);
            uint2 r[4];
            #pragma unroll
            for (int q = 0; q < 4; q++)
                r[q] = __ldg(inh + (size_t)si[q] * 32 + lane);
            #pragma unroll
            for (int q = 0; q < 4; q++)
                acc_row(acc, r[q]);
            j += 4;
        }
        for (; j < n; j++) {
            int sj = __shfl_sync(0xffffffffu, s, j);
            uint2 r = __ldg(inh + (size_t)sj * 32 + lane);
            acc_row(acc, r);
        }
    }
    ((float4*)out)[(size_t)node * 32 + lane] = acc;
}

// ---------------------------------------------------------------------------
// GEMM: out[r,c] = din_is[r] * (A[r,:] @ W[:,c]) + bias[c], D=128 square,
// with BN column stats (sum, sumsq of out) fused into the epilogue.
// Block: 64 rows x 128 cols, 256 threads, 8 rows x 4 cols per thread.
// Inner loop: packed fma.rn.f32x2 over row pairs.
// ---------------------------------------------------------------------------
#define SMEM128 ((128 * 128 + 128 * 68 + 256) * 4)

__global__ void __launch_bounds__(256) gemm128_kernel(
    const float* __restrict__ A, const float* __restrict__ W,
    const float* __restrict__ bias, float* __restrict__ out, int N)
{
    extern __shared__ float sm[];
    float* sW   = sm;                        // [k][c], 128*128
    float* sAT  = sm + 128 * 128;            // [k][r], leading dim 68
    float* sSum = sAT + 128 * 68;            // [128]
    float* sSq  = sSum + 128;                // [128]
    int tid  = threadIdx.x;
    int row0 = blockIdx.x * 64;

    if (tid < 128) { sSum[tid] = 0.f; sSq[tid] = 0.f; }

    {
        const float4* W4 = (const float4*)W;
        float4* sW4 = (float4*)sW;
        #pragma unroll
        for (int i = 0; i < 16; i++) sW4[tid + i * 256] = __ldg(W4 + tid + i * 256);
    }
    #pragma unroll
    for (int ii = 0; ii < 8; ii++) {
        int i  = tid + ii * 256;           // 2048 float4 total
        int r  = i >> 5;
        int k4 = (i & 31) << 2;
        int rr = row0 + r;
        float4 v = make_float4(0.f, 0.f, 0.f, 0.f);
        if (rr < N) v = __ldg((const float4*)(A + (size_t)rr * 128 + k4));
        sAT[(k4 + 0) * 68 + r] = v.x;
        sAT[(k4 + 1) * 68 + r] = v.y;
        sAT[(k4 + 2) * 68 + r] = v.z;
        sAT[(k4 + 3) * 68 + r] = v.w;
    }
    __syncthreads();

    int cg = (tid & 31) << 2;   // cols [cg, cg+4)
    int rg = (tid >> 5) << 3;   // rows [rg, rg+8)

    unsigned long long accp[4][4];
    #pragma unroll
    for (int pr = 0; pr < 4; pr++)
        #pragma unroll
        for (int j = 0; j < 4; j++) accp[pr][j] = 0ull;

    #pragma unroll 8
    for (int k = 0; k < 128; k++) {
        float4 wv = *(const float4*)(sW + k * 128 + cg);
        const ulonglong2* apt = (const ulonglong2*)(sAT + k * 68 + rg);
        ulonglong2 a01 = apt[0];
        ulonglong2 a23 = apt[1];
        unsigned long long ap[4] = {a01.x, a01.y, a23.x, a23.y};
        unsigned long long wd[4];
        PACKF2(wd[0], wv.x, wv.x);
        PACKF2(wd[1], wv.y, wv.y);
        PACKF2(wd[2], wv.z, wv.z);
        PACKF2(wd[3], wv.w, wv.w);
        #pragma unroll
        for (int pr = 0; pr < 4; pr++)
            #pragma unroll
            for (int j = 0; j < 4; j++)
                FMA_F32X2(accp[pr][j], ap[pr], wd[j], accp[pr][j]);
    }

    float acc[8][4];
    #pragma unroll
    for (int pr = 0; pr < 4; pr++)
        #pragma unroll
        for (int j = 0; j < 4; j++) {
            float lo, hi;
            UNPACKF2(lo, hi, accp[pr][j]);
            acc[2 * pr + 0][j] = lo;
            acc[2 * pr + 1][j] = hi;
        }

    float4 bv = __ldg((const float4*)(bias + cg));
    float csum[4] = {0.f, 0.f, 0.f, 0.f};
    float csq[4]  = {0.f, 0.f, 0.f, 0.f};
    #pragma unroll
    for (int i = 0; i < 8; i++) {
        int rr = row0 + rg + i;
        if (rr < N) {
            float sc = __ldg(&g_din_is[rr]);
            float4 o;
            o.x = fmaf(acc[i][0], sc, bv.x);
            o.y = fmaf(acc[i][1], sc, bv.y);
            o.z = fmaf(acc[i][2], sc, bv.z);
            o.w = fmaf(acc[i][3], sc, bv.w);
            csum[0] += o.x; csq[0] = fmaf(o.x, o.x, csq[0]);
            csum[1] += o.y; csq[1] = fmaf(o.y, o.y, csq[1]);
            csum[2] += o.z; csq[2] = fmaf(o.z, o.z, csq[2]);
            csum[3] += o.w; csq[3] = fmaf(o.w, o.w, csq[3]);
            *(float4*)(out + (size_t)rr * 128 + cg) = o;
        }
    }
    #pragma unroll
    for (int j = 0; j < 4; j++) {
        atomicAdd(&sSum[cg + j], csum[j]);
        atomicAdd(&sSq[cg + j],  csq[j]);
    }
    __syncthreads();
    if (tid < 128) {
        atomicAdd(&g_colsum[tid], sSum[tid]);
        atomicAdd(&g_colsq[tid],  sSq[tid]);
    }
}

__global__ void bn_finalize_kernel(const float* __restrict__ g,
                                   const float* __restrict__ be, float invN) {
    int c = threadIdx.x;  // 128 threads
    float mu  = g_colsum[c] * invN;
    float var = fmaf(-mu, mu, g_colsq[c] * invN);
    float a   = __ldg(g + c) * rsqrtf(var + 1e-5f);
    g_bn_a[c] = a;
    g_bn_b[c] = fmaf(-mu, a, __ldg(be + c));
    g_colsum[c] = 0.f;  // reset for next BN / next launch
    g_colsq[c]  = 0.f;
}

// ---------------------------------------------------------------------------
// Layer-3 pre-prop GEMM: t[r, 0..39] = dout_is[r] * (relu(bn(A[r,:])) @ W3).
// BN+ReLU applied while staging A. f32x2 packed FMA over row pairs.
// ---------------------------------------------------------------------------
#define SMEM40 ((128 * 64 + 128 * 68) * 4)

__global__ void __launch_bounds__(256) gemm40pre_kernel(
    const float* __restrict__ A, const float* __restrict__ W3,
    float* __restrict__ t, int N)
{
    extern __shared__ float sm[];
    float* sW   = sm;                       // [k][c] padded to 64 cols
    float* sAT  = sm + 128 * 64;            // [k][r] ld 68
    int tid  = threadIdx.x;
    int row0 = blockIdx.x * 64;

    for (int i = tid; i < 128 * 64; i += 256) sW[i] = 0.f;
    __syncthreads();
    for (int i = tid; i < 128 * 40; i += 256) {
        int k = i / 40, c = i - k * 40;
        sW[k * 64 + c] = __ldg(W3 + i);
    }
    #pragma unroll
    for (int ii = 0; ii < 8; ii++) {
        int i  = tid + ii * 256;
        int r  = i >> 5;
        int k4 = (i & 31) << 2;
        int rr = row0 + r;
        float4 v = make_float4(0.f, 0.f, 0.f, 0.f);
        if (rr < N) v = __ldg((const float4*)(A + (size_t)rr * 128 + k4));
        float4 a = __ldg(((const float4*)g_bn_a) + (k4 >> 2));
        float4 b = __ldg(((const float4*)g_bn_b) + (k4 >> 2));
        sAT[(k4 + 0) * 68 + r] = fmaxf(fmaf(v.x, a.x, b.x), 0.f);
        sAT[(k4 + 1) * 68 + r] = fmaxf(fmaf(v.y, a.y, b.y), 0.f);
        sAT[(k4 + 2) * 68 + r] = fmaxf(fmaf(v.z, a.z, b.z), 0.f);
        sAT[(k4 + 3) * 68 + r] = fmaxf(fmaf(v.w, a.w, b.w), 0.f);
    }
    __syncthreads();

    int cg = (tid & 15) << 2;   // cols [cg, cg+4) of 64 (only <40 real)
    int rg = (tid >> 4) << 2;   // rows [rg, rg+4)

    unsigned long long accp[2][4];   // row pairs (rg,rg+1),(rg+2,rg+3)
    #pragma unroll
    for (int pr = 0; pr < 2; pr++)
        #pragma unroll
        for (int j = 0; j < 4; j++) accp[pr][j] = 0ull;

    #pragma unroll 8
    for (int k = 0; k < 128; k++) {
        float4 wv = *(const float4*)(sW + k * 64 + cg);
        ulonglong2 a01 = *(const ulonglong2*)(sAT + k * 68 + rg);
        unsigned long long ap[2] = {a01.x, a01.y};
        unsigned long long wd[4];
        PACKF2(wd[0], wv.x, wv.x);
        PACKF2(wd[1], wv.y, wv.y);
        PACKF2(wd[2], wv.z, wv.z);
        PACKF2(wd[3], wv.w, wv.w);
        #pragma unroll
        for (int pr = 0; pr < 2; pr++)
            #pragma unroll
            for (int j = 0; j < 4; j++)
                FMA_F32X2(accp[pr][j], ap[pr], wd[j], accp[pr][j]);
    }

    float acc[4][4];
    #pragma unroll
    for (int pr = 0; pr < 2; pr++)
        #pragma unroll
        for (int j = 0; j < 4; j++) {
            float lo, hi;
            UNPACKF2(lo, hi, accp[pr][j]);
            acc[2 * pr + 0][j] = lo;
            acc[2 * pr + 1][j] = hi;
        }

    if (cg < 40) {
        #pragma unroll
        for (int i = 0; i < 4; i++) {
            int rr = row0 + rg + i;
            if (rr < N) {
                float sc = __ldg(&g_dout_is[rr]);
                float4 o;
                o.x = acc[i][0] * sc;
                o.y = acc[i][1] * sc;
                o.z = acc[i][2] * sc;
                o.w = acc[i][3] * sc;
                *(float4*)(t + (size_t)rr * 40 + cg) = o;
            }
        }
    }
}

// ---------------------------------------------------------------------------
// 40-wide CSR propagation + bias + log_softmax. One warp per dst node.
// Lanes 0..9 each own 4 of the 40 features (float4, fp32 for final precision).
// ---------------------------------------------------------------------------
__global__ void __launch_bounds__(256) prop40_kernel(
    const float* __restrict__ t, const float* __restrict__ b3,
    float* __restrict__ out, int N)
{
    int node = blockIdx.x * 8 + (threadIdx.x >> 5);
    if (node >= N) return;
    int lane = threadIdx.x & 31;
    bool act = lane < 10;
    int start = __ldg(&g_row_off[node]);
    int end   = __ldg(&g_row_off[node + 1]);

    float4 acc = make_float4(0.f, 0.f, 0.f, 0.f);
    for (int base = start; base < end; base += 32) {
        int n = min(32, end - base);
        int s = 0;
        if (lane < n) s = __ldg(g_csr_src + base + lane);
        int j = 0;
        for (; j + 4 <= n; j += 4) {
            int s0 = __shfl_sync(0xffffffffu, s, j);
            int s1 = __shfl_sync(0xffffffffu, s, j + 1);
            int s2 = __shfl_sync(0xffffffffu, s, j + 2);
            int s3 = __shfl_sync(0xffffffffu, s, j + 3);
            if (act) {
                float4 v0 = __ldg((const float4*)(t + (size_t)s0 * 40) + lane);
                float4 v1 = __ldg((const float4*)(t + (size_t)s1 * 40) + lane);
                float4 v2 = __ldg((const float4*)(t + (size_t)s2 * 40) + lane);
                float4 v3 = __ldg((const float4*)(t + (size_t)s3 * 40) + lane);
                acc.x += v0.x + v1.x + v2.x + v3.x;
                acc.y += v0.y + v1.y + v2.y + v3.y;
                acc.z += v0.z + v1.z + v2.z + v3.z;
                acc.w += v0.w + v1.w + v2.w + v3.w;
            }
        }
        for (; j < n; j++) {
            int sj = __shfl_sync(0xffffffffu, s, j);
            if (act) {
                float4 v = __ldg((const float4*)(t + (size_t)sj * 40) + lane);
                acc.x += v.x; acc.y += v.y; acc.z += v.z; acc.w += v.w;
            }
        }
    }

    float din = __ldg(&g_din_is[node]);
    float4 o = make_float4(0.f, 0.f, 0.f, 0.f);
    if (act) {
        float4 bv = __ldg(((const float4*)b3) + lane);
        o.x = fmaf(acc.x, din, bv.x);
        o.y = fmaf(acc.y, din, bv.y);
        o.z = fmaf(acc.z, din, bv.z);
        o.w = fmaf(acc.w, din, bv.w);
    }
    float m = act ? fmaxf(fmaxf(o.x, o.y), fmaxf(o.z, o.w)) : -1e30f;
    #pragma unroll
    for (int off = 16; off; off >>= 1)
        m = fmaxf(m, __shfl_xor_sync(0xffffffffu, m, off));
    float e = act ? (expf(o.x - m) + expf(o.y - m) +
                     expf(o.z - m) + expf(o.w - m)) : 0.f;
    #pragma unroll
    for (int off = 16; off; off >>= 1)
        e += __shfl_xor_sync(0xffffffffu, e, off);
    float lse = m + logf(e);
    if (act) {
        float4 r;
        r.x = o.x - lse; r.y = o.y - lse; r.z = o.z - lse; r.w = o.w - lse;
        *(float4*)(out + (size_t)node * 40 + lane * 4) = r;
    }
}

// ---------------------------------------------------------------------------
extern "C" void kernel_launch(void* const* d_in, const int* in_sizes, int n_in,
                              void* d_out, int out_size)
{
    const float* x   = (const float*)d_in[0];
    const int*   src = (const int*)d_in[1];
    const int*   dst = (const int*)d_in[2];
    const float* W1  = (const float*)d_in[3];
    const float* b1  = (const float*)d_in[4];
    const float* g1  = (const float*)d_in[5];
    const float* be1 = (const float*)d_in[6];
    const float* W2  = (const float*)d_in[7];
    const float* b2  = (const float*)d_in[8];
    const float* g2  = (const float*)d_in[9];
    const float* be2 = (const float*)d_in[10];
    const float* W3  = (const float*)d_in[11];
    const float* b3  = (const float*)d_in[12];

    int N = in_sizes[0] / DD;
    int E = in_sizes[1];
    float* out = (float*)d_out;

    float *bufA, *bufB;
    __half2* bufH;
    cudaGetSymbolAddress((void**)&bufA, g_bufA);
    cudaGetSymbolAddress((void**)&bufB, g_bufB);
    cudaGetSymbolAddress((void**)&bufH, g_half);

    cudaFuncSetAttribute(gemm128_kernel,
                         cudaFuncAttributeMaxDynamicSharedMemorySize, SMEM128);
    cudaFuncSetAttribute(gemm40pre_kernel,
                         cudaFuncAttributeMaxDynamicSharedMemorySize, SMEM40);

    int ngrid  = (N + 255) / 256;
    int egrid  = (E + 255) / 256;
    int pgrid  = (N + 7) / 8;          // 8 warps (nodes) per 256-thread block
    int qgrid  = (N * 32 + 255) / 256; // prep: one thread per float4
    int ggrid  = (N + 63) / 64;
    int chunk  = (N + CHUNKS - 1) / CHUNKS;
    float invN = 1.0f / (float)N;

    // degrees + CSR-by-dst
    zero_deg_kernel<<<ngrid, 256>>>(N);
    deg_count_kernel<<<egrid, 256>>>(src, dst, E);
    deg_inv_kernel<<<ngrid, 256>>>(N);
    chunk_sum_kernel<<<CHUNKS / 8, 256>>>(N, chunk);
    scan_chunks_kernel<<<1, 1024>>>(N);
    fill_off_kernel<<<CHUNKS / 8, 256>>>(N, chunk);
    csr_fill_kernel<<<egrid, 256>>>(src, dst, E);

    // layer 1
    prep_kernel<0><<<qgrid, 256>>>((const float4*)x, bufH, N);
    prop_fp16_kernel<<<pgrid, 256>>>((const uint2*)bufH, bufA, N);
    gemm128_kernel<<<ggrid, 256, SMEM128>>>(bufA, W1, b1, bufB, N);
    bn_finalize_kernel<<<1, 128>>>(g1, be1, invN);

    // layer 2
    prep_kernel<1><<<qgrid, 256>>>((const float4*)bufB, bufH, N);
    prop_fp16_kernel<<<pgrid, 256>>>((const uint2*)bufH, bufA, N);
    gemm128_kernel<<<ggrid, 256, SMEM128>>>(bufA, W2, b2, bufB, N);
    bn_finalize_kernel<<<1, 128>>>(g2, be2, invN);

    // layer 3: GEMM first (prop and @W3 commute), then 40-wide prop
    //          with fused bias + log_softmax (fp32 for output precision)
    gemm40pre_kernel<<<ggrid, 256, SMEM40>>>(bufB, W3, bufA, N);
    prop40_kernel<<<pgrid, 256>>>(bufA, b3, out, N);
}